// round 4
// baseline (speedup 1.0000x reference)
#include <cuda_runtime.h>

#define B_ 128
#define T_ 1024
#define I_ 128
#define H_ 256
#define O_ 64

// Scratch (device globals — no allocations allowed)
__device__ float g_xw[(size_t)B_ * T_ * H_];  // 128 MB: x @ W_xh^T + b_h
__device__ float g_hs[(size_t)B_ * T_ * H_];  // 128 MB: hidden states

// ---------------------------------------------------------------------------
// Packed f32x2 helpers (sm_103a FFMA2 path)
// ---------------------------------------------------------------------------
__device__ __forceinline__ void ffma2(unsigned long long &acc,
                                      unsigned long long a,
                                      unsigned long long b) {
    asm("fma.rn.f32x2 %0, %1, %2, %0;" : "+l"(acc) : "l"(a), "l"(b));
}
__device__ __forceinline__ unsigned long long dup2(float a) {
    unsigned long long r;
    asm("mov.b64 %0, {%1, %1};" : "=l"(r) : "f"(a));
    return r;
}
__device__ __forceinline__ float2 unpack2(unsigned long long v) {
    float2 r;
    asm("mov.b64 {%0, %1}, %2;" : "=f"(r.x), "=f"(r.y) : "l"(v));
    return r;
}

// ---------------------------------------------------------------------------
// Phase 1: g_xw[row,h] = sum_i x[row,i] * W_xh[h,i] + b_h[h]
// NT GEMM: M=131072 rows, N=256, K=128. Tile 128x256 (full N), 256 threads,
// thread computes 8 rows x 8 f32x2 col-pairs (16 n). FFMA2 fraction ~76%.
// ---------------------------------------------------------------------------
#define P1_APAD 132
#define P1_BPAD 260
#define P1_SMEM ((128 * P1_APAD + 128 * P1_BPAD) * 4)

__global__ __launch_bounds__(256, 1) void p1_kernel(
    const float* __restrict__ x, const float* __restrict__ Wxh,
    const float* __restrict__ bh) {
    extern __shared__ float sm[];
    float* As  = sm;                    // [128 m][P1_APAD] (m x k)
    float* BsT = sm + 128 * P1_APAD;    // [128 k][P1_BPAD] (k x n)
    const int tid = threadIdx.x;
    const int mt = blockIdx.x;

    // A tile: 128 rows of x, coalesced float4
    const float* Ag = x + (size_t)mt * 128 * I_;
#pragma unroll
    for (int i = 0; i < 16; i++) {
        int lin = tid + 256 * i;
        int r = lin >> 5, c4 = lin & 31;
        float4 v = ((const float4*)Ag)[r * 32 + c4];
        *(float4*)(As + r * P1_APAD + c4 * 4) = v;
    }
    // B tile transposed: BsT[k][n] = Wxh[n][k], n = tid
    {
        const float4* Bg = (const float4*)(Wxh + (size_t)tid * I_);
#pragma unroll 8
        for (int q = 0; q < 32; q++) {
            float4 v = Bg[q];
            int kb = q * 4;
            BsT[(kb + 0) * P1_BPAD + tid] = v.x;
            BsT[(kb + 1) * P1_BPAD + tid] = v.y;
            BsT[(kb + 2) * P1_BPAD + tid] = v.z;
            BsT[(kb + 3) * P1_BPAD + tid] = v.w;
        }
    }
    __syncthreads();

    const int tx = tid & 15, ty = tid >> 4;
    unsigned long long acc[8][8];
#pragma unroll
    for (int u = 0; u < 8; u++)
#pragma unroll
        for (int v = 0; v < 8; v++) acc[u][v] = 0ull;

#pragma unroll 4
    for (int k = 0; k < 128; k++) {
        unsigned long long a2[8];
        ulonglong2 bb[4];
#pragma unroll
        for (int u = 0; u < 8; u++)
            a2[u] = dup2(As[(ty + 16 * u) * P1_APAD + k]);
#pragma unroll
        for (int v = 0; v < 4; v++)
            bb[v] = *(const ulonglong2*)(BsT + k * P1_BPAD + 4 * tx + 64 * v);
#pragma unroll
        for (int u = 0; u < 8; u++)
#pragma unroll
            for (int v = 0; v < 4; v++) {
                ffma2(acc[u][2 * v],     a2[u], bb[v].x);
                ffma2(acc[u][2 * v + 1], a2[u], bb[v].y);
            }
    }

    float4 bias[4];
#pragma unroll
    for (int v = 0; v < 4; v++)
        bias[v] = *(const float4*)(bh + 4 * tx + 64 * v);
#pragma unroll
    for (int u = 0; u < 8; u++) {
        size_t row = (size_t)mt * 128 + ty + 16 * u;
        float* op = g_xw + row * H_;
#pragma unroll
        for (int v = 0; v < 4; v++) {
            float2 r0 = unpack2(acc[u][2 * v]);
            float2 r1 = unpack2(acc[u][2 * v + 1]);
            float4 o;
            o.x = r0.x + bias[v].x;
            o.y = r0.y + bias[v].y;
            o.z = r1.x + bias[v].z;
            o.w = r1.y + bias[v].w;
            *(float4*)(op + 4 * tx + 64 * v) = o;
        }
    }
}

// ---------------------------------------------------------------------------
// Phase 2: sequential scan. 1 CTA per batch (128 CTAs), 512 threads (16 warps).
// Each h-dot is split across an even/odd lane pair (k-halves of 128), reduced
// with shfl.bfly(1). W_hh row-half per thread: 40 u64 in registers,
// 24 u64 in smem ([j][tid], conflict-free). h double-buffered in smem;
// xW prefetched one step ahead. One barrier per step.
// ---------------------------------------------------------------------------
#define NJR2 40  // u64 W pairs in registers per thread (k-offsets 0..79)
#define NJS2 24  // u64 W pairs in smem per thread      (k-offsets 80..127)
#define RNN_SMEM (NJS2 * 512 * 8 + 2 * H_ * 4)

__global__ __launch_bounds__(512, 1) void rnn_kernel(
    const float* __restrict__ Whh) {
    extern __shared__ char smraw[];
    unsigned long long* Wsm = (unsigned long long*)smraw;  // [NJS2][512]
    float* hb = (float*)(smraw + NJS2 * 512 * 8);          // [2][H_]
    const int tid = threadIdx.x;
    const int lane = tid & 31;
    const int w = tid >> 5;
    const int h = (w << 4) | (lane >> 1);
    const int half = lane & 1;
    const int b = blockIdx.x;

    const unsigned long long* wrow =
        (const unsigned long long*)(Whh + (size_t)h * H_ + half * 128);
    unsigned long long wreg[NJR2];
#pragma unroll
    for (int j = 0; j < NJR2; j++) wreg[j] = wrow[j];
#pragma unroll
    for (int j = 0; j < NJS2; j++) Wsm[j * 512 + tid] = wrow[NJR2 + j];
    hb[tid] = 0.0f;  // tid 0..511 covers both buffers (2*H_ = 512)
    __syncthreads();

    const float* xwp = g_xw + (size_t)b * T_ * H_ + h;
    float* hsp = g_hs + (size_t)b * T_ * H_ + h;
    float xw_cur = xwp[0];
    int cur = 0;

#pragma unroll 1
    for (int t = 0; t < T_; t++) {
        float xw_nxt = __ldg(xwp + (size_t)((t + 1) & (T_ - 1)) * H_);
        const ulonglong2* h2 = (const ulonglong2*)(hb + cur * H_ + half * 128);
        unsigned long long acc0 = 0ull, acc1 = 0ull;
        // register part of W: k-offsets 0..79
#pragma unroll
        for (int j = 0; j < NJR2 / 2; j++) {
            ulonglong2 hv = h2[j];  // LDS.128, 2 broadcast groups per warp
            ffma2(acc0, hv.x, wreg[2 * j]);
            ffma2(acc1, hv.y, wreg[2 * j + 1]);
        }
        // smem part of W: k-offsets 80..127
#pragma unroll
        for (int j = 0; j < NJS2 / 2; j++) {
            ulonglong2 hv = h2[NJR2 / 2 + j];
            ffma2(acc0, hv.x, Wsm[(2 * j) * 512 + tid]);
            ffma2(acc1, hv.y, Wsm[(2 * j + 1) * 512 + tid]);
        }
        float2 a0 = unpack2(acc0), a1 = unpack2(acc1);
        float s = (a0.x + a0.y) + (a1.x + a1.y);
        s += __shfl_xor_sync(0xffffffffu, s, 1);  // combine the two k-halves
        float hnew = fmaxf(xw_cur + s, 0.0f);
        if (!half) {
            hb[(cur ^ 1) * H_ + h] = hnew;
            hsp[(size_t)t * H_] = hnew;
        }
        xw_cur = xw_nxt;
        cur ^= 1;
        __syncthreads();
    }
}

// ---------------------------------------------------------------------------
// Phase 3: out[row,o] = sum_h g_hs[row,h] * W_out[o,h] + b_out[o]
// M=131072, N=64, K=256. Tile 128 rows x 64 cols.
// ---------------------------------------------------------------------------
#define P3_WPAD 66
#define P3_APAD 68
#define P3_SMEM ((256 * P3_WPAD + 128 * P3_APAD) * 4)

__global__ __launch_bounds__(256, 1) void p3_kernel(
    const float* __restrict__ Wout, const float* __restrict__ bout,
    float* __restrict__ out) {
    extern __shared__ float sm[];
    float* WsT = sm;                    // [256 k][P3_WPAD] (k x o)
    float* As  = sm + 256 * P3_WPAD;    // [128 m][P3_APAD] (m x k-chunk)
    const int tid = threadIdx.x;
    const int mt = blockIdx.x;

    // Stage W_out transposed: WsT[k][o] = Wout[o][k]
    {
        int o = tid >> 2, kq = tid & 3;
        const float4* Wg = (const float4*)(Wout + (size_t)o * H_ + kq * 64);
#pragma unroll
        for (int q = 0; q < 16; q++) {
            float4 v = Wg[q];
            int kb = kq * 64 + q * 4;
            WsT[(kb + 0) * P3_WPAD + o] = v.x;
            WsT[(kb + 1) * P3_WPAD + o] = v.y;
            WsT[(kb + 2) * P3_WPAD + o] = v.z;
            WsT[(kb + 3) * P3_WPAD + o] = v.w;
        }
    }

    const int tx = tid & 15, ty = tid >> 4;
    unsigned long long acc[8][2];
#pragma unroll
    for (int u = 0; u < 8; u++) { acc[u][0] = 0ull; acc[u][1] = 0ull; }

    for (int kc = 0; kc < 4; kc++) {
        __syncthreads();
#pragma unroll
        for (int i = 0; i < 8; i++) {
            int lin = tid + 256 * i;
            int r = lin >> 4, c4 = lin & 15;
            float4 v = *(const float4*)(g_hs + ((size_t)mt * 128 + r) * H_ +
                                        kc * 64 + c4 * 4);
            *(float4*)(As + r * P3_APAD + c4 * 4) = v;
        }
        __syncthreads();
#pragma unroll 4
        for (int k = 0; k < 64; k++) {
            unsigned long long b0 = *(const unsigned long long*)(
                WsT + (kc * 64 + k) * P3_WPAD + 2 * tx);
            unsigned long long b1 = *(const unsigned long long*)(
                WsT + (kc * 64 + k) * P3_WPAD + 2 * tx + 32);
#pragma unroll
            for (int u = 0; u < 8; u++) {
                unsigned long long a2 = dup2(As[(ty + 16 * u) * P3_APAD + k]);
                ffma2(acc[u][0], a2, b0);
                ffma2(acc[u][1], a2, b1);
            }
        }
    }

    float2 bias0 = *(const float2*)(bout + 2 * tx);
    float2 bias1 = *(const float2*)(bout + 2 * tx + 32);
#pragma unroll
    for (int u = 0; u < 8; u++) {
        size_t row = (size_t)mt * 128 + ty + 16 * u;
        float2 r0 = unpack2(acc[u][0]);
        float2 r1 = unpack2(acc[u][1]);
        r0.x += bias0.x; r0.y += bias0.y;
        r1.x += bias1.x; r1.y += bias1.y;
        *(float2*)(out + row * O_ + 2 * tx) = r0;
        *(float2*)(out + row * O_ + 2 * tx + 32) = r1;
    }
}

// ---------------------------------------------------------------------------
extern "C" void kernel_launch(void* const* d_in, const int* in_sizes, int n_in,
                              void* d_out, int out_size) {
    const float* x    = (const float*)d_in[0];
    const float* Wxh  = (const float*)d_in[1];
    const float* Whh  = (const float*)d_in[2];
    const float* bh   = (const float*)d_in[3];
    const float* Wout = (const float*)d_in[4];
    const float* bout = (const float*)d_in[5];
    float* out = (float*)d_out;

    cudaFuncSetAttribute(p1_kernel, cudaFuncAttributeMaxDynamicSharedMemorySize, P1_SMEM);
    cudaFuncSetAttribute(rnn_kernel, cudaFuncAttributeMaxDynamicSharedMemorySize, RNN_SMEM);
    cudaFuncSetAttribute(p3_kernel, cudaFuncAttributeMaxDynamicSharedMemorySize, P3_SMEM);

    p1_kernel<<<B_ * T_ / 128, 256, P1_SMEM>>>(x, Wxh, bh);
    rnn_kernel<<<B_, 512, RNN_SMEM>>>(Whh);
    p3_kernel<<<B_ * T_ / 128, 256, P3_SMEM>>>(Wout, bout, out);
}

// round 5
// speedup vs baseline: 1.4817x; 1.4817x over previous
#include <cuda_runtime.h>

#define B_ 128
#define T_ 1024
#define I_ 128
#define H_ 256
#define O_ 64

// Scratch (device globals — no allocations allowed)
__device__ float g_xw[(size_t)B_ * T_ * H_];  // 128 MB: x @ W_xh^T + b_h
__device__ float g_hs[(size_t)B_ * T_ * H_];  // 128 MB: hidden states

// ---------------------------------------------------------------------------
// Packed f32x2 helpers (sm_103a FFMA2 path)
// ---------------------------------------------------------------------------
__device__ __forceinline__ void ffma2(unsigned long long &acc,
                                      unsigned long long a,
                                      unsigned long long b) {
    asm("fma.rn.f32x2 %0, %1, %2, %0;" : "+l"(acc) : "l"(a), "l"(b));
}
__device__ __forceinline__ unsigned long long dup2(float a) {
    unsigned long long r;
    asm("mov.b64 %0, {%1, %1};" : "=l"(r) : "f"(a));
    return r;
}
__device__ __forceinline__ float2 unpack2(unsigned long long v) {
    float2 r;
    asm("mov.b64 {%0, %1}, %2;" : "=f"(r.x), "=f"(r.y) : "l"(v));
    return r;
}

// ---------------------------------------------------------------------------
// Phase 1: g_xw[row,h] = sum_i x[row,i] * W_xh[h,i] + b_h[h]
// NT GEMM: M=131072 rows, N=256, K=128. Tile 128x128, 256 threads,
// thread computes 8 rows x 4 f32x2-col-pairs.  (R2 version, known 213us)
// ---------------------------------------------------------------------------
#define P1_PAD 132
#define P1_SMEM ((128 * P1_PAD + 128 * P1_PAD) * 4)

__global__ __launch_bounds__(256, 1) void p1_kernel(
    const float* __restrict__ x, const float* __restrict__ Wxh,
    const float* __restrict__ bh) {
    extern __shared__ float sm[];
    float* As  = sm;                  // [128 m][P1_PAD] (m x k)
    float* BsT = sm + 128 * P1_PAD;   // [128 k][P1_PAD] (k x n)
    const int tid = threadIdx.x;
    const int mt = blockIdx.x >> 1;
    const int nt = blockIdx.x & 1;

    const float* Ag = x + (size_t)mt * 128 * I_;
#pragma unroll
    for (int i = 0; i < 16; i++) {
        int lin = tid + 256 * i;
        int r = lin >> 5, c4 = lin & 31;
        float4 v = ((const float4*)Ag)[r * 32 + c4];
        *(float4*)(As + r * P1_PAD + c4 * 4) = v;
    }
    {
        int n = tid & 127, kg = tid >> 7;
        const float4* Bg = (const float4*)(Wxh + (size_t)(nt * 128 + n) * I_ + kg * 64);
#pragma unroll
        for (int q = 0; q < 16; q++) {
            float4 v = Bg[q];
            int kb = kg * 64 + q * 4;
            BsT[(kb + 0) * P1_PAD + n] = v.x;
            BsT[(kb + 1) * P1_PAD + n] = v.y;
            BsT[(kb + 2) * P1_PAD + n] = v.z;
            BsT[(kb + 3) * P1_PAD + n] = v.w;
        }
    }
    __syncthreads();

    const int tx = tid & 15, ty = tid >> 4;
    unsigned long long acc[8][4];
#pragma unroll
    for (int u = 0; u < 8; u++)
#pragma unroll
        for (int v = 0; v < 4; v++) acc[u][v] = 0ull;

#pragma unroll 4
    for (int k = 0; k < 128; k++) {
        unsigned long long a2[8], b2[4];
#pragma unroll
        for (int u = 0; u < 8; u++)
            a2[u] = dup2(As[(ty + 16 * u) * P1_PAD + k]);
#pragma unroll
        for (int v = 0; v < 4; v++)
            b2[v] = *(const unsigned long long*)(BsT + k * P1_PAD + 2 * tx + 32 * v);
#pragma unroll
        for (int u = 0; u < 8; u++)
#pragma unroll
            for (int v = 0; v < 4; v++) ffma2(acc[u][v], a2[u], b2[v]);
    }

    float2 bias[4];
#pragma unroll
    for (int v = 0; v < 4; v++)
        bias[v] = *(const float2*)(bh + nt * 128 + 2 * tx + 32 * v);
#pragma unroll
    for (int u = 0; u < 8; u++) {
        size_t row = (size_t)mt * 128 + ty + 16 * u;
        float* op = g_xw + row * H_ + nt * 128;
#pragma unroll
        for (int v = 0; v < 4; v++) {
            float2 r = unpack2(acc[u][v]);
            r.x += bias[v].x;
            r.y += bias[v].y;
            *(float2*)(op + 2 * tx + 32 * v) = r;
        }
    }
}

// ---------------------------------------------------------------------------
// Phase 2: sequential scan. 1 CTA per batch (128 CTAs), 256 threads.
// Thread h computes h_new[h]. W_hh row h: k in [0,192) in registers
// (96 packed u64), k in [192,256) in smem ([j][h] conflict-free).
// Fixes vs R2: 4-deep xW register FIFO (hides DRAM latency), explicit
// software-pipelined h loads (rotating hv/hvn), 4 accumulator chains.
// ---------------------------------------------------------------------------
#define NJR 96  // register f32x2 pairs per thread (k = 0..191)
#define NJS 32  // smem   f32x2 pairs per h       (k = 192..255)
#define RNN_SMEM (NJS * H_ * 8 + 2 * H_ * 4)
#define XF 4    // xW prefetch FIFO depth

__global__ __launch_bounds__(256, 1) void rnn_kernel(
    const float* __restrict__ Whh) {
    extern __shared__ float sm[];
    unsigned long long* WsmU = (unsigned long long*)sm;   // [NJS][H_]
    float* hb = sm + NJS * H_ * 2;                        // [2][H_]
    const int h = threadIdx.x;
    const int b = blockIdx.x;

    const float* wrow = Whh + (size_t)h * H_;
    unsigned long long wreg[NJR];
#pragma unroll
    for (int j = 0; j < NJR; j++)
        wreg[j] = ((const unsigned long long*)wrow)[j];
#pragma unroll
    for (int j = 0; j < NJS; j++)
        WsmU[j * H_ + h] = ((const unsigned long long*)wrow)[NJR + j];
    hb[h] = 0.0f;
    hb[H_ + h] = 0.0f;

    const float* xwp = g_xw + (size_t)b * T_ * H_ + h;
    float* hsp = g_hs + (size_t)b * T_ * H_ + h;

    float xwf[XF];
#pragma unroll
    for (int i = 0; i < XF; i++)
        xwf[i] = __ldg(xwp + (size_t)i * H_);
    __syncthreads();

    int cur = 0;
#pragma unroll 1
    for (int t = 0; t < T_; t++) {
        const ulonglong2* h2 = (const ulonglong2*)(hb + cur * H_);
        unsigned long long acc0 = 0ull, acc1 = 0ull, acc2 = 0ull, acc3 = 0ull;

        // software-pipelined: prefetch next iteration's h chunk before use
        ulonglong2 hv = h2[0];
        // register part: 48 iterations (k = 0..191)
#pragma unroll
        for (int j = 0; j < NJR / 2; j++) {
            ulonglong2 hvn = h2[j + 1];  // safe: j+1 <= 48 < 64 total chunks
            if (j & 1) {
                ffma2(acc2, hv.x, wreg[2 * j]);
                ffma2(acc3, hv.y, wreg[2 * j + 1]);
            } else {
                ffma2(acc0, hv.x, wreg[2 * j]);
                ffma2(acc1, hv.y, wreg[2 * j + 1]);
            }
            hv = hvn;
        }
        // smem part: 16 iterations (k = 192..255); hv already holds chunk 48
#pragma unroll
        for (int j = 0; j < NJS / 2; j++) {
            ulonglong2 hvn = (j < NJS / 2 - 1) ? h2[NJR / 2 + j + 1] : hv;
            unsigned long long w0 = WsmU[(2 * j) * H_ + h];
            unsigned long long w1 = WsmU[(2 * j + 1) * H_ + h];
            if (j & 1) {
                ffma2(acc2, hv.x, w0);
                ffma2(acc3, hv.y, w1);
            } else {
                ffma2(acc0, hv.x, w0);
                ffma2(acc1, hv.y, w1);
            }
            hv = hvn;
        }

        float2 a0 = unpack2(acc0), a1 = unpack2(acc1);
        float2 a2 = unpack2(acc2), a3 = unpack2(acc3);
        float s = ((a0.x + a0.y) + (a1.x + a1.y)) +
                  ((a2.x + a2.y) + (a3.x + a3.y));
        float hnew = fmaxf(xwf[t & (XF - 1)] + s, 0.0f);
        hb[(cur ^ 1) * H_ + h] = hnew;
        hsp[(size_t)t * H_] = hnew;
        // refill FIFO slot: prefetch step t+XF (wrapped; wrapped loads unused)
        xwf[t & (XF - 1)] = __ldg(xwp + (size_t)((t + XF) & (T_ - 1)) * H_);
        cur ^= 1;
        __syncthreads();
    }
}

// ---------------------------------------------------------------------------
// Phase 3: out[row,o] = sum_h g_hs[row,h] * W_out[o,h] + b_out[o]
// M=131072, N=64, K=256. Tile 128 rows x 64 cols.
// ---------------------------------------------------------------------------
#define P3_WPAD 66
#define P3_APAD 68
#define P3_SMEM ((256 * P3_WPAD + 128 * P3_APAD) * 4)

__global__ __launch_bounds__(256, 1) void p3_kernel(
    const float* __restrict__ Wout, const float* __restrict__ bout,
    float* __restrict__ out) {
    extern __shared__ float sm[];
    float* WsT = sm;                    // [256 k][P3_WPAD] (k x o)
    float* As  = sm + 256 * P3_WPAD;    // [128 m][P3_APAD] (m x k-chunk)
    const int tid = threadIdx.x;
    const int mt = blockIdx.x;

    {
        int o = tid >> 2, kq = tid & 3;
        const float4* Wg = (const float4*)(Wout + (size_t)o * H_ + kq * 64);
#pragma unroll
        for (int q = 0; q < 16; q++) {
            float4 v = Wg[q];
            int kb = kq * 64 + q * 4;
            WsT[(kb + 0) * P3_WPAD + o] = v.x;
            WsT[(kb + 1) * P3_WPAD + o] = v.y;
            WsT[(kb + 2) * P3_WPAD + o] = v.z;
            WsT[(kb + 3) * P3_WPAD + o] = v.w;
        }
    }

    const int tx = tid & 15, ty = tid >> 4;
    unsigned long long acc[8][2];
#pragma unroll
    for (int u = 0; u < 8; u++) { acc[u][0] = 0ull; acc[u][1] = 0ull; }

    for (int kc = 0; kc < 4; kc++) {
        __syncthreads();
#pragma unroll
        for (int i = 0; i < 8; i++) {
            int lin = tid + 256 * i;
            int r = lin >> 4, c4 = lin & 15;
            float4 v = *(const float4*)(g_hs + ((size_t)mt * 128 + r) * H_ +
                                        kc * 64 + c4 * 4);
            *(float4*)(As + r * P3_APAD + c4 * 4) = v;
        }
        __syncthreads();
#pragma unroll 4
        for (int k = 0; k < 64; k++) {
            unsigned long long b0 = *(const unsigned long long*)(
                WsT + (kc * 64 + k) * P3_WPAD + 2 * tx);
            unsigned long long b1 = *(const unsigned long long*)(
                WsT + (kc * 64 + k) * P3_WPAD + 2 * tx + 32);
#pragma unroll
            for (int u = 0; u < 8; u++) {
                unsigned long long a2 = dup2(As[(ty + 16 * u) * P3_APAD + k]);
                ffma2(acc[u][0], a2, b0);
                ffma2(acc[u][1], a2, b1);
            }
        }
    }

    float2 bias0 = *(const float2*)(bout + 2 * tx);
    float2 bias1 = *(const float2*)(bout + 2 * tx + 32);
#pragma unroll
    for (int u = 0; u < 8; u++) {
        size_t row = (size_t)mt * 128 + ty + 16 * u;
        float2 r0 = unpack2(acc[u][0]);
        float2 r1 = unpack2(acc[u][1]);
        r0.x += bias0.x; r0.y += bias0.y;
        r1.x += bias1.x; r1.y += bias1.y;
        *(float2*)(out + row * O_ + 2 * tx) = r0;
        *(float2*)(out + row * O_ + 2 * tx + 32) = r1;
    }
}

// ---------------------------------------------------------------------------
extern "C" void kernel_launch(void* const* d_in, const int* in_sizes, int n_in,
                              void* d_out, int out_size) {
    const float* x    = (const float*)d_in[0];
    const float* Wxh  = (const float*)d_in[1];
    const float* Whh  = (const float*)d_in[2];
    const float* bh   = (const float*)d_in[3];
    const float* Wout = (const float*)d_in[4];
    const float* bout = (const float*)d_in[5];
    float* out = (float*)d_out;

    cudaFuncSetAttribute(p1_kernel, cudaFuncAttributeMaxDynamicSharedMemorySize, P1_SMEM);
    cudaFuncSetAttribute(rnn_kernel, cudaFuncAttributeMaxDynamicSharedMemorySize, RNN_SMEM);
    cudaFuncSetAttribute(p3_kernel, cudaFuncAttributeMaxDynamicSharedMemorySize, P3_SMEM);

    p1_kernel<<<(B_ * T_ / 128) * 2, 256, P1_SMEM>>>(x, Wxh, bh);
    rnn_kernel<<<B_, 256, RNN_SMEM>>>(Whh);
    p3_kernel<<<B_ * T_ / 128, 256, P3_SMEM>>>(Wout, bout, out);
}